// round 14
// baseline (speedup 1.0000x reference)
#include <cuda_runtime.h>
#include <cuda_fp16.h>
#include <math.h>
#include <stdint.h>

#define BB 2
#define SS 2048
#define DD 1024
#define HH 16
#define DH 64
#define MTOT (BB*SS)
#define MATF ((size_t)MTOT * DD)

// ---------------------------------------------------------------------------
// Scratch (all fp16 operand storage; word-permuted for LDS.64 fragments)
// ---------------------------------------------------------------------------
__device__ __half g_QKVh[3 * MTOT * DD]; // Q|K: [B,H,S,Dh] d-word-perm (Q pre-scaled);
                                         // Vt: [B,H,Dh,S] s-word-perm
__device__ __half g_atth[MTOT * DD];     // [B,S,D] fp16, d-word-perm (matches WoT)
__device__ __half g_WTh[4 * DD * DD];    // K-major transposed weights, k-word-perm
__device__ __half g_Xh[MTOT * DD];       // X fp16, k-word-perm

// ---------------------------------------------------------------------------
// helpers.  Word perm within 8-word (16-half) groups: word w sits at
// pos(w)=2*(w&3)+((w>>2)&1); thread tig's mma k-words {tig, tig+4} land
// adjacent -> one 8B LDS per fragment pair.
// ---------------------------------------------------------------------------
__device__ __forceinline__ void mma16(float* c, const uint32_t* a,
                                      uint32_t b0, uint32_t b1) {
    asm volatile("mma.sync.aligned.m16n8k16.row.col.f32.f16.f16.f32 "
        "{%0,%1,%2,%3}, {%4,%5,%6,%7}, {%8,%9}, {%0,%1,%2,%3};"
        : "+f"(c[0]), "+f"(c[1]), "+f"(c[2]), "+f"(c[3])
        : "r"(a[0]), "r"(a[1]), "r"(a[2]), "r"(a[3]), "r"(b0), "r"(b1));
}
__device__ __forceinline__ uint32_t smem_u32(const void* p) {
    uint32_t a;
    asm("{ .reg .u64 t; cvta.to.shared.u64 t, %1; cvt.u32.u64 %0, t; }"
        : "=r"(a) : "l"(p));
    return a;
}
__device__ __forceinline__ void cp_async16(uint32_t dst, const void* src) {
    asm volatile("cp.async.cg.shared.global [%0], [%1], 16;" :: "r"(dst), "l"(src));
}
#define CP_COMMIT() asm volatile("cp.async.commit_group;" ::: "memory")
#define CP_WAIT0()  asm volatile("cp.async.wait_group 0;" ::: "memory")
#define CP_WAIT1()  asm volatile("cp.async.wait_group 1;" ::: "memory")

__device__ __forceinline__ uint32_t pack_h2(float a, float b) {
    __half2 h = __floats2half2_rn(a, b);
    return *(uint32_t*)&h;
}

// ---------------------------------------------------------------------------
// X -> fp16 word-permuted copy
// ---------------------------------------------------------------------------
__global__ __launch_bounds__(256)
void conv_half(const float* __restrict__ in, __half* __restrict__ outp) {
    const size_t i = ((size_t)blockIdx.x * 256 + threadIdx.x) * 16;
    __half2* o2 = (__half2*)(outp + i);
    #pragma unroll
    for (int w = 0; w < 8; w++) {
        const int wp = 2 * (w & 3) + (w >> 2);
        o2[wp] = __floats2half2_rn(in[i + 2 * w], in[i + 2 * w + 1]);
    }
}

// ---------------------------------------------------------------------------
// Weight transpose + fp16 + k-word-perm: Wt[z][n][perm16(k)] = h(W_z[k][n])
// ---------------------------------------------------------------------------
__global__ __launch_bounds__(256)
void transpose4(const float* __restrict__ W0, const float* __restrict__ W1,
                const float* __restrict__ W2, const float* __restrict__ W3,
                __half* __restrict__ Wt) {
    __shared__ float t[32][33];
    const int z = blockIdx.z;
    const float* W = (z == 0) ? W0 : (z == 1) ? W1 : (z == 2) ? W2 : W3;
    __half* Wd = Wt + (size_t)z * DD * DD;
    const int bx = blockIdx.x * 32, by = blockIdx.y * 32;
    const int x = threadIdx.x & 31, y = threadIdx.x >> 5;
    #pragma unroll
    for (int i = 0; i < 32; i += 8)
        t[y + i][x] = W[(size_t)(by + y + i) * DD + bx + x];
    __syncthreads();
    #pragma unroll
    for (int i = 0; i < 32; i += 8) {
        const int k = by + x;
        const int w = k >> 1;
        const int wp = (w & ~7) | (2 * (w & 3) + ((w >> 2) & 1));
        Wd[(size_t)(bx + y + i) * DD + 2 * wp + (k & 1)] =
            __float2half_rn(t[x][y + i]);
    }
}

// ---------------------------------------------------------------------------
// fp16 mma.sync GEMM: BK=32 halves, 3-stage cp.async (wait depth 2 -> each
// load gets two compute phases to land). One barrier per stage.
// MODE 0: fused QKV -> fp16 outputs; MODE 1: fp32 final GEMM.
// ---------------------------------------------------------------------------
#define GBK 32                         // halves per stage
#define GSTR 24                        // row stride in 4B words (16 + 8 pad)
#define GSTAGE (128 * GSTR)            // 3072 words per matrix per stage
#define GNS (DD / GBK)                 // 32
#define GEMM_SMEM_BYTES (3 * 2 * GSTAGE * 4)   // 73728

#define QSCALE 0.18033688011112042f    // 0.125 * log2(e)

template<int MODE>
__global__ __launch_bounds__(256, 2)
void gemm_tc(const __half* __restrict__ A, const __half* __restrict__ WtBase,
             const float* __restrict__ b0, const float* __restrict__ b1,
             const float* __restrict__ b2, void* __restrict__ C0) {
    extern __shared__ float gsm[];

    const int z = (MODE == 0) ? blockIdx.z : 0;
    const __half* Wt = WtBase + (size_t)z * DD * DD;
    const float* bias = (z == 0) ? b0 : (z == 1) ? b1 : b2;

    const int tid = threadIdx.x;
    const int lane = tid & 31, wid = tid >> 5;
    const int gid = lane >> 2, tig = lane & 3;
    const int wm = (wid >> 1) * 32;
    const int wn = (wid & 1) * 64;
    const int m0 = blockIdx.y * 128, n0 = blockIdx.x * 128;

    const __half* Ag = A  + (size_t)m0 * DD;
    const __half* Bg = Wt + (size_t)n0 * DD;
    const uint32_t sbase = smem_u32(gsm);

    auto prefetch = [&](int s, int st) {
        if (s < GNS) {
            const uint32_t As = sbase + (uint32_t)(st * 2 * GSTAGE) * 4u;
            const uint32_t Bs = As + GSTAGE * 4u;
            #pragma unroll
            for (int i = 0; i < 2; i++) {
                const int idx = tid + i * 256;        // 0..511
                const int row = idx >> 2, c = idx & 3;
                const uint32_t so = (uint32_t)(row * GSTR + c * 4) * 4u;
                cp_async16(As + so, Ag + (size_t)row * DD + s * GBK + c * 8);
                cp_async16(Bs + so, Bg + (size_t)row * DD + s * GBK + c * 8);
            }
        }
        CP_COMMIT();
    };

    prefetch(0, 0);
    prefetch(1, 1);

    float cacc[2][8][4] = {};

    for (int s = 0; s < GNS; s++) {
        const int st = s % 3;
        CP_WAIT1();                      // stage s landed (s+1 may still fly)
        __syncthreads();                 // publish; stage s-1 buffer now free
        prefetch(s + 2, (s + 2) % 3);    // overwrite stage s-1's buffer
        const uint32_t* Ab = (const uint32_t*)gsm + st * 2 * GSTAGE;
        const uint32_t* Bb = Ab + GSTAGE;
        #pragma unroll
        for (int kb = 0; kb < 2; kb++) {
            uint32_t af[2][4];
            #pragma unroll
            for (int mt = 0; mt < 2; mt++) {
                const int r = wm + mt * 16 + gid;
                uint2 lo = *(const uint2*)&Ab[r * GSTR + kb * 8 + 2 * tig];
                uint2 hi = *(const uint2*)&Ab[(r + 8) * GSTR + kb * 8 + 2 * tig];
                af[mt][0] = lo.x; af[mt][1] = hi.x;
                af[mt][2] = lo.y; af[mt][3] = hi.y;
            }
            #pragma unroll
            for (int nt = 0; nt < 8; nt++) {
                const int n = wn + nt * 8 + gid;
                uint2 bv = *(const uint2*)&Bb[n * GSTR + kb * 8 + 2 * tig];
                mma16(cacc[0][nt], af[0], bv.x, bv.y);
                mma16(cacc[1][nt], af[1], bv.x, bv.y);
            }
        }
    }

    float breg[8][2];
    #pragma unroll
    for (int nt = 0; nt < 8; nt++) {
        const int n = n0 + wn + nt * 8 + 2 * tig;
        breg[nt][0] = bias[n];
        breg[nt][1] = bias[n + 1];
    }
    #pragma unroll
    for (int mt = 0; mt < 2; mt++) {
        const int mA = m0 + wm + mt * 16 + gid;
        const int mB = mA + 8;
        #pragma unroll
        for (int nt = 0; nt < 8; nt++) {
            const int n = n0 + wn + nt * 8 + 2 * tig;
            float v0 = cacc[mt][nt][0] + breg[nt][0];
            float v1 = cacc[mt][nt][1] + breg[nt][1];
            float v2 = cacc[mt][nt][2] + breg[nt][0];
            float v3 = cacc[mt][nt][3] + breg[nt][1];
            if (MODE == 0) {
                __half* Hout = ((__half*)C0) + (size_t)z * MATF;
                const int bA = mA >> 11, sA = mA & (SS - 1);
                const int bB = mB >> 11, sB = mB & (SS - 1);
                const int h = n >> 6, d = n & 63;          // d even
                if (z < 2) {
                    const float qs = (z == 0) ? QSCALE : 1.0f;
                    const int w = d >> 1;
                    const int wp = (w & ~7) | (2 * (w & 3) + ((w >> 2) & 1));
                    __half2* H2 = (__half2*)Hout;
                    H2[((size_t)(bA * HH + h) * SS + sA) * 32 + wp] =
                        __floats2half2_rn(v0 * qs, v1 * qs);
                    H2[((size_t)(bB * HH + h) * SS + sB) * 32 + wp] =
                        __floats2half2_rn(v2 * qs, v3 * qs);
                } else {
                    auto hpos = [](int sc) {
                        int w = sc >> 1;
                        int wp = (w & ~7) | (2 * (w & 3) + ((w >> 2) & 1));
                        return 2 * wp + (sc & 1);
                    };
                    const int pA = hpos(sA), pB = hpos(sB);
                    const size_t rA0 = ((size_t)(bA * HH + h) * DH + d) * SS;
                    const size_t rA1 = rA0 + SS;
                    const size_t rB0 = ((size_t)(bB * HH + h) * DH + d) * SS;
                    const size_t rB1 = rB0 + SS;
                    Hout[rA0 + pA] = __float2half_rn(v0);
                    Hout[rA1 + pA] = __float2half_rn(v1);
                    Hout[rB0 + pB] = __float2half_rn(v2);
                    Hout[rB1 + pB] = __float2half_rn(v3);
                }
            } else {
                float* C = (float*)C0;
                C[(size_t)mA * DD + n]     = v0;
                C[(size_t)mA * DD + n + 1] = v1;
                C[(size_t)mB * DD + n]     = v2;
                C[(size_t)mB * DD + n + 1] = v3;
            }
        }
    }
}

// ---------------------------------------------------------------------------
// Flash attention, fp16 mma, register-resident P. Pipeline stage now carries
// TWO j-tiles (128 K-rows + 128 V-cols): per-stage wait/barrier/prefetch
// events halve (16 stages), computed as two 64-wide passes (same registers).
// ---------------------------------------------------------------------------
#define KSTA 40                          // K row stride (32 d-words + 8)
#define VSTA 72                          // V row stride (64 j-words + 8)
#define KWA (128 * KSTA)                 // 5120 words (128 j-rows)
#define VWA (64 * VSTA)                  // 4608 words (64 d-rows x 128 j)
#define STAGEWA (KWA + VWA)              // 9728 words = 38912 B
#define NSTG (SS / 128)                  // 16
#define ATT_SMEM_BYTES (2 * STAGEWA * 4)         // 77824

__global__ __launch_bounds__(256, 2)
void attn_tc(const __half* __restrict__ Qh, const __half* __restrict__ Kh,
             const __half* __restrict__ Vth, __half* __restrict__ O) {
    extern __shared__ uint32_t smu[];
    uint32_t* stage = smu;                      // 2 x (K[128][KSTA] + Vt[64][VSTA])

    const int tid = threadIdx.x, lane = tid & 31, wid = tid >> 5;
    const int gid = lane >> 2, tig = lane & 3;
    const int q0 = blockIdx.x * 128;
    const int h = blockIdx.y, b = blockIdx.z;

    const __half* Qb = Qh  + ((size_t)(b * HH + h) * SS) * DH;
    const __half* Kb = Kh  + ((size_t)(b * HH + h) * SS) * DH;
    const __half* Vb = Vth + ((size_t)(b * HH + h) * DH) * SS;   // [Dh][S]
    const uint32_t stb = smem_u32(stage);

    auto prefetch = [&](int ts, int st) {
        if (ts < NSTG) {
            const __half* Kg = Kb + (size_t)ts * 128 * DH;
            const __half* Vg = Vb + (size_t)ts * 128;
            const uint32_t Ka = stb + (uint32_t)(st * STAGEWA) * 4u;
            const uint32_t Va = Ka + KWA * 4u;
            #pragma unroll
            for (int i = 0; i < 4; i++) {
                const int idx = tid + i * 256;          // 0..1023
                // K: 128 rows x 8 chunks of 16B
                const int kr = idx >> 3, kc = idx & 7;
                cp_async16(Ka + (uint32_t)(kr * KSTA + kc * 4) * 4u,
                           Kg + (size_t)kr * DH + kc * 8);
                // V: 64 rows x 16 chunks of 16B
                const int vr = idx >> 4, vc = idx & 15;
                cp_async16(Va + (uint32_t)(vr * VSTA + vc * 4) * 4u,
                           Vg + (size_t)vr * SS + vc * 8);
            }
        }
        CP_COMMIT();
    };

    prefetch(0, 0);

    const int rloc = wid * 16 + gid;

    // Q A-fragments to registers (fp16, word-permuted, pre-scaled)
    uint32_t qf[4][4];
    {
        const uint32_t* Qw1 = (const uint32_t*)(Qb + (size_t)(q0 + rloc) * DH);
        const uint32_t* Qw2 = Qw1 + 8 * 32;
        #pragma unroll
        for (int kb = 0; kb < 4; kb++) {
            uint2 lo = *(const uint2*)&Qw1[kb * 8 + 2 * tig];
            uint2 hi = *(const uint2*)&Qw2[kb * 8 + 2 * tig];
            qf[kb][0] = lo.x; qf[kb][1] = hi.x;
            qf[kb][2] = lo.y; qf[kb][3] = hi.y;
        }
    }

    float l1 = 0.f, l2 = 0.f;
    float acc[8][4] = {};

    for (int ts = 0; ts < NSTG; ts++) {
        const int st = ts & 1;
        CP_WAIT0();                       // stage ts landed
        __syncthreads();                  // publish; other stage buffer free
        prefetch(ts + 1, st ^ 1);
        const uint32_t* Kw = stage + st * STAGEWA;
        const uint32_t* Vw = Kw + KWA;

        #pragma unroll
        for (int jh = 0; jh < 2; jh++) {
            // S' = Q' @ K^T over 64 j-columns (Q' pre-scaled so P = exp2(S'))
            float sc[8][4] = {};
            #pragma unroll
            for (int kb = 0; kb < 4; kb++) {
                #pragma unroll
                for (int nt = 0; nt < 8; nt++) {
                    uint2 bv = *(const uint2*)
                        &Kw[(jh * 64 + nt * 8 + gid) * KSTA + kb * 8 + 2 * tig];
                    mma16(sc[nt], qf[kb], bv.x, bv.y);
                }
            }
            // PV with register-resident P
            #pragma unroll
            for (int kb = 0; kb < 4; kb++) {
                const float e00 = exp2f(sc[2*kb][0]),   e01 = exp2f(sc[2*kb][1]);
                const float e02 = exp2f(sc[2*kb][2]),   e03 = exp2f(sc[2*kb][3]);
                const float e10 = exp2f(sc[2*kb+1][0]), e11 = exp2f(sc[2*kb+1][1]);
                const float e12 = exp2f(sc[2*kb+1][2]), e13 = exp2f(sc[2*kb+1][3]);
                l1 += e00 + e01 + e10 + e11;
                l2 += e02 + e03 + e12 + e13;
                uint32_t af[4];
                af[0] = pack_h2(e00, e01);
                af[1] = pack_h2(e02, e03);
                af[2] = pack_h2(e10, e11);
                af[3] = pack_h2(e12, e13);
                #pragma unroll
                for (int nt = 0; nt < 8; nt++) {
                    uint2 bv = *(const uint2*)
                        &Vw[(nt * 8 + gid) * VSTA + jh * 32 + kb * 8 + 2 * tig];
                    mma16(acc[nt], af, bv.x, bv.y);
                }
            }
        }
    }

    // final row-sum reduce + normalize + fp16 word-permuted store [B,S,D]
    l1 += __shfl_xor_sync(0xffffffffu, l1, 1);
    l1 += __shfl_xor_sync(0xffffffffu, l1, 2);
    l2 += __shfl_xor_sync(0xffffffffu, l2, 1);
    l2 += __shfl_xor_sync(0xffffffffu, l2, 2);
    const float inv1 = 1.0f / l1, inv2 = 1.0f / l2;
    const int r1 = q0 + rloc, r2 = r1 + 8;
    __half2* O2 = (__half2*)O;
    #pragma unroll
    for (int nt = 0; nt < 8; nt++) {
        const int wlog = h * 32 + nt * 4 + tig;
        const int wp = (wlog & ~7) | (2 * (wlog & 3) + ((wlog >> 2) & 1));
        O2[((size_t)b * SS + r1) * (DD / 2) + wp] =
            __floats2half2_rn(acc[nt][0] * inv1, acc[nt][1] * inv1);
        O2[((size_t)b * SS + r2) * (DD / 2) + wp] =
            __floats2half2_rn(acc[nt][2] * inv2, acc[nt][3] * inv2);
    }
}

// ---------------------------------------------------------------------------
extern "C" void kernel_launch(void* const* d_in, const int* in_sizes, int n_in,
                              void* d_out, int out_size) {
    const float* X  = (const float*)d_in[0];
    const float* Wq = (const float*)d_in[1];
    const float* bq = (const float*)d_in[2];
    const float* Wk = (const float*)d_in[3];
    const float* bk = (const float*)d_in[4];
    const float* Wv = (const float*)d_in[5];
    const float* bv = (const float*)d_in[6];
    const float* Wo = (const float*)d_in[7];
    const float* bo = (const float*)d_in[8];
    float* out = (float*)d_out;

    __half *dqkvh, *datth, *dwth, *dxh;
    cudaGetSymbolAddress((void**)&dqkvh, g_QKVh);
    cudaGetSymbolAddress((void**)&datth, g_atth);
    cudaGetSymbolAddress((void**)&dwth,  g_WTh);
    cudaGetSymbolAddress((void**)&dxh,   g_Xh);
    __half* dq = dqkvh;
    __half* dk = dqkvh + MATF;
    __half* dv = dqkvh + 2 * MATF;
    __half* WoT = dwth + 3 * (size_t)DD * DD;

    cudaFuncSetAttribute(attn_tc,
                         cudaFuncAttributeMaxDynamicSharedMemorySize, ATT_SMEM_BYTES);
    cudaFuncSetAttribute(gemm_tc<0>,
                         cudaFuncAttributeMaxDynamicSharedMemorySize, GEMM_SMEM_BYTES);
    cudaFuncSetAttribute(gemm_tc<1>,
                         cudaFuncAttributeMaxDynamicSharedMemorySize, GEMM_SMEM_BYTES);

    conv_half<<<(int)(MATF / (256 * 16)), 256>>>(X, dxh);
    dim3 tgrid(DD / 32, DD / 32, 4);
    transpose4<<<tgrid, 256>>>(Wq, Wk, Wv, Wo, dwth);

    dim3 qkvgrid(DD / 128, MTOT / 128, 3);   // (8, 32, 3)
    gemm_tc<0><<<qkvgrid, 256, GEMM_SMEM_BYTES>>>(dxh, dwth, bq, bk, bv, (void*)dqkvh);

    dim3 agrid(SS / 128, HH, BB);            // (16, 16, 2)
    attn_tc<<<agrid, 256, ATT_SMEM_BYTES>>>(dq, dk, dv, datth);

    dim3 ogrid(DD / 128, MTOT / 128);        // (8, 32)
    gemm_tc<1><<<ogrid, 256, GEMM_SMEM_BYTES>>>(datth, WoT, bo, nullptr, nullptr, (void*)out);
}

// round 15
// speedup vs baseline: 1.0995x; 1.0995x over previous
#include <cuda_runtime.h>
#include <cuda_fp16.h>
#include <math.h>
#include <stdint.h>

#define BB 2
#define SS 2048
#define DD 1024
#define HH 16
#define DH 64
#define MTOT (BB*SS)
#define MATF ((size_t)MTOT * DD)

// ---------------------------------------------------------------------------
// Scratch (fp16 operand storage, CANONICAL layouts — ldmatrix does the
// fragment shuffling in hardware)
// ---------------------------------------------------------------------------
__device__ __half g_QKVh[3 * MTOT * DD]; // Q|K: [B,H,S,Dh] (Q pre-scaled by 0.125*log2e);
                                         // Vt: [B,H,Dh,S]
__device__ __half g_atth[MTOT * DD];     // [B,S,D] fp16
__device__ __half g_WTh[4 * DD * DD];    // K-major transposed weights
__device__ __half g_Xh[MTOT * DD];       // X fp16

// ---------------------------------------------------------------------------
// helpers
// ---------------------------------------------------------------------------
__device__ __forceinline__ void mma16(float* c, const uint32_t* a,
                                      uint32_t b0, uint32_t b1) {
    asm volatile("mma.sync.aligned.m16n8k16.row.col.f32.f16.f16.f32 "
        "{%0,%1,%2,%3}, {%4,%5,%6,%7}, {%8,%9}, {%0,%1,%2,%3};"
        : "+f"(c[0]), "+f"(c[1]), "+f"(c[2]), "+f"(c[3])
        : "r"(a[0]), "r"(a[1]), "r"(a[2]), "r"(a[3]), "r"(b0), "r"(b1));
}
__device__ __forceinline__ void ldsm4(uint32_t& r0, uint32_t& r1,
                                      uint32_t& r2, uint32_t& r3, uint32_t addr) {
    asm volatile("ldmatrix.sync.aligned.m8n8.x4.shared.b16 {%0,%1,%2,%3}, [%4];"
        : "=r"(r0), "=r"(r1), "=r"(r2), "=r"(r3) : "r"(addr));
}
__device__ __forceinline__ uint32_t smem_u32(const void* p) {
    uint32_t a;
    asm("{ .reg .u64 t; cvta.to.shared.u64 t, %1; cvt.u32.u64 %0, t; }"
        : "=r"(a) : "l"(p));
    return a;
}
__device__ __forceinline__ void cp_async16(uint32_t dst, const void* src) {
    asm volatile("cp.async.cg.shared.global [%0], [%1], 16;" :: "r"(dst), "l"(src));
}
#define CP_COMMIT() asm volatile("cp.async.commit_group;" ::: "memory")
#define CP_WAIT0()  asm volatile("cp.async.wait_group 0;" ::: "memory")
#define CP_WAIT1()  asm volatile("cp.async.wait_group 1;" ::: "memory")

__device__ __forceinline__ uint32_t pack_h2(float a, float b) {
    __half2 h = __floats2half2_rn(a, b);
    return *(uint32_t*)&h;
}

// ---------------------------------------------------------------------------
// X -> fp16 copy (canonical)
// ---------------------------------------------------------------------------
__global__ __launch_bounds__(256)
void conv_half(const float* __restrict__ in, __half* __restrict__ outp) {
    const size_t i = ((size_t)blockIdx.x * 256 + threadIdx.x) * 16;
    __half2* o2 = (__half2*)(outp + i);
    #pragma unroll
    for (int w = 0; w < 8; w++)
        o2[w] = __floats2half2_rn(in[i + 2 * w], in[i + 2 * w + 1]);
}

// ---------------------------------------------------------------------------
// Weight transpose + fp16 (canonical): Wt[z][n][k] = h(W_z[k][n])
// ---------------------------------------------------------------------------
__global__ __launch_bounds__(256)
void transpose4(const float* __restrict__ W0, const float* __restrict__ W1,
                const float* __restrict__ W2, const float* __restrict__ W3,
                __half* __restrict__ Wt) {
    __shared__ float t[32][33];
    const int z = blockIdx.z;
    const float* W = (z == 0) ? W0 : (z == 1) ? W1 : (z == 2) ? W2 : W3;
    __half* Wd = Wt + (size_t)z * DD * DD;
    const int bx = blockIdx.x * 32, by = blockIdx.y * 32;
    const int x = threadIdx.x & 31, y = threadIdx.x >> 5;
    #pragma unroll
    for (int i = 0; i < 32; i += 8)
        t[y + i][x] = W[(size_t)(by + y + i) * DD + bx + x];
    __syncthreads();
    #pragma unroll
    for (int i = 0; i < 32; i += 8)
        Wd[(size_t)(bx + y + i) * DD + (by + x)] = __float2half_rn(t[x][y + i]);
}

// ---------------------------------------------------------------------------
// fp16 mma.sync GEMM: BK=64 halves, 2-stage cp.async, one barrier/stage,
// ldmatrix.x4 for A and B fragments.
// MODE 0: fused QKV -> fp16 outputs; MODE 1: fp32 final GEMM.
// ---------------------------------------------------------------------------
#define GBK 64                         // halves per stage
#define GSTR 36                        // row stride in 4B words (32 + 4 pad)
#define GSTAGE (128 * GSTR)            // 4608 words per matrix per stage
#define GNS (DD / GBK)                 // 16
#define GEMM_SMEM_BYTES (2 * 2 * GSTAGE * 4)   // 73728

#define QSCALE 0.18033688011112042f    // 0.125 * log2(e)

template<int MODE>
__global__ __launch_bounds__(256, 2)
void gemm_tc(const __half* __restrict__ A, const __half* __restrict__ WtBase,
             const float* __restrict__ b0, const float* __restrict__ b1,
             const float* __restrict__ b2, void* __restrict__ C0) {
    extern __shared__ float gsm[];

    const int z = (MODE == 0) ? blockIdx.z : 0;
    const __half* Wt = WtBase + (size_t)z * DD * DD;
    const float* bias = (z == 0) ? b0 : (z == 1) ? b1 : b2;

    const int tid = threadIdx.x;
    const int lane = tid & 31, wid = tid >> 5;
    const int gid = lane >> 2, tig = lane & 3;
    const int wm = (wid >> 1) * 32;
    const int wn = (wid & 1) * 64;
    const int m0 = blockIdx.y * 128, n0 = blockIdx.x * 128;

    const __half* Ag = A  + (size_t)m0 * DD;
    const __half* Bg = Wt + (size_t)n0 * DD;
    const uint32_t sbase = smem_u32(gsm);

    // ldmatrix lane-dependent word offsets
    const uint32_t aoffw = (uint32_t)((wm + (lane & 15)) * GSTR + (lane >> 4) * 4);
    const uint32_t boffw = (uint32_t)((wn + (lane & 7) + (lane >> 4) * 8) * GSTR
                                      + ((lane >> 3) & 1) * 4);

    auto prefetch = [&](int s, int st) {
        if (s < GNS) {
            const uint32_t As = sbase + (uint32_t)(st * 2 * GSTAGE) * 4u;
            const uint32_t Bs = As + GSTAGE * 4u;
            #pragma unroll
            for (int i = 0; i < 4; i++) {
                const int idx = tid + i * 256;        // 0..1023
                const int row = idx >> 3, c = idx & 7;
                const uint32_t so = (uint32_t)(row * GSTR + c * 4) * 4u;
                cp_async16(As + so, Ag + (size_t)row * DD + s * GBK + c * 8);
                cp_async16(Bs + so, Bg + (size_t)row * DD + s * GBK + c * 8);
            }
        }
        CP_COMMIT();
    };

    prefetch(0, 0);

    float cacc[2][8][4] = {};

    for (int s = 0; s < GNS; s++) {
        const int st = s & 1;
        CP_WAIT0();
        __syncthreads();
        prefetch(s + 1, st ^ 1);
        const uint32_t Abase = sbase + (uint32_t)(st * 2 * GSTAGE) * 4u;
        const uint32_t Bbase = Abase + GSTAGE * 4u;
        #pragma unroll
        for (int kb = 0; kb < 4; kb++) {
            uint32_t af[2][4];
            #pragma unroll
            for (int mt = 0; mt < 2; mt++)
                ldsm4(af[mt][0], af[mt][1], af[mt][2], af[mt][3],
                      Abase + (aoffw + (uint32_t)(mt * 16 * GSTR + kb * 8)) * 4u);
            #pragma unroll
            for (int np = 0; np < 4; np++) {
                uint32_t bv0, bv1, bv2, bv3;
                ldsm4(bv0, bv1, bv2, bv3,
                      Bbase + (boffw + (uint32_t)(np * 16 * GSTR + kb * 8)) * 4u);
                mma16(cacc[0][2*np],   af[0], bv0, bv1);
                mma16(cacc[0][2*np+1], af[0], bv2, bv3);
                mma16(cacc[1][2*np],   af[1], bv0, bv1);
                mma16(cacc[1][2*np+1], af[1], bv2, bv3);
            }
        }
    }

    float breg[8][2];
    #pragma unroll
    for (int nt = 0; nt < 8; nt++) {
        const int n = n0 + wn + nt * 8 + 2 * tig;
        breg[nt][0] = bias[n];
        breg[nt][1] = bias[n + 1];
    }
    #pragma unroll
    for (int mt = 0; mt < 2; mt++) {
        const int mA = m0 + wm + mt * 16 + gid;
        const int mB = mA + 8;
        #pragma unroll
        for (int nt = 0; nt < 8; nt++) {
            const int n = n0 + wn + nt * 8 + 2 * tig;
            float v0 = cacc[mt][nt][0] + breg[nt][0];
            float v1 = cacc[mt][nt][1] + breg[nt][1];
            float v2 = cacc[mt][nt][2] + breg[nt][0];
            float v3 = cacc[mt][nt][3] + breg[nt][1];
            if (MODE == 0) {
                __half* Hout = ((__half*)C0) + (size_t)z * MATF;
                const int bA = mA >> 11, sA = mA & (SS - 1);
                const int bB = mB >> 11, sB = mB & (SS - 1);
                const int h = n >> 6, d = n & 63;          // d even
                if (z < 2) {
                    const float qs = (z == 0) ? QSCALE : 1.0f;
                    __half2* H2 = (__half2*)Hout;
                    H2[((size_t)(bA * HH + h) * SS + sA) * 32 + (d >> 1)] =
                        __floats2half2_rn(v0 * qs, v1 * qs);
                    H2[((size_t)(bB * HH + h) * SS + sB) * 32 + (d >> 1)] =
                        __floats2half2_rn(v2 * qs, v3 * qs);
                } else {
                    const size_t rA0 = ((size_t)(bA * HH + h) * DH + d) * SS;
                    const size_t rA1 = rA0 + SS;
                    const size_t rB0 = ((size_t)(bB * HH + h) * DH + d) * SS;
                    const size_t rB1 = rB0 + SS;
                    Hout[rA0 + sA] = __float2half_rn(v0);
                    Hout[rA1 + sA] = __float2half_rn(v1);
                    Hout[rB0 + sB] = __float2half_rn(v2);
                    Hout[rB1 + sB] = __float2half_rn(v3);
                }
            } else {
                float* C = (float*)C0;
                C[(size_t)mA * DD + n]     = v0;
                C[(size_t)mA * DD + n + 1] = v1;
                C[(size_t)mB * DD + n]     = v2;
                C[(size_t)mB * DD + n + 1] = v3;
            }
        }
    }
}

// ---------------------------------------------------------------------------
// Flash attention, fp16 mma, register-resident P, ldmatrix.x4 for K and V
// B-fragments. 3-stage cp.async pipeline (64-row tiles, wait depth 1).
// ---------------------------------------------------------------------------
#define HST 36
#define KW (64 * HST)
#define VW (64 * HST)
#define STAGEW (KW + VW)
#define NTILE (SS / 64)
#define ATT_SMEM_BYTES (3 * STAGEW * 4)         // 55296

__global__ __launch_bounds__(256, 2)
void attn_tc(const __half* __restrict__ Qh, const __half* __restrict__ Kh,
             const __half* __restrict__ Vth, __half* __restrict__ O) {
    extern __shared__ uint32_t smu[];
    uint32_t* stage = smu;                      // 3 x (K[64][HST] + Vt[64][HST])

    const int tid = threadIdx.x, lane = tid & 31, wid = tid >> 5;
    const int gid = lane >> 2, tig = lane & 3;
    const int q0 = blockIdx.x * 128;
    const int h = blockIdx.y, b = blockIdx.z;

    const __half* Qb = Qh  + ((size_t)(b * HH + h) * SS) * DH;
    const __half* Kb = Kh  + ((size_t)(b * HH + h) * SS) * DH;
    const __half* Vb = Vth + ((size_t)(b * HH + h) * DH) * SS;   // [Dh][S]
    const uint32_t stb = smem_u32(stage);

    // ldmatrix lane-dependent word offset (B pattern, rows within 16-row pair)
    const uint32_t boffw = (uint32_t)(((lane & 7) + (lane >> 4) * 8) * HST
                                      + ((lane >> 3) & 1) * 4);

    auto prefetch = [&](int jt, int st) {
        if (jt < NTILE) {
            const __half* Kg = Kb + (size_t)jt * 64 * DH;
            const __half* Vg = Vb + (size_t)jt * 64;
            const uint32_t Ka = stb + (uint32_t)(st * STAGEW) * 4u;
            const uint32_t Va = Ka + KW * 4u;
            #pragma unroll
            for (int i = 0; i < 2; i++) {
                const int idx = tid + i * 256;
                const int r = idx >> 3, c = idx & 7;
                cp_async16(Ka + (uint32_t)(r * HST + c * 4) * 4u,
                           Kg + (size_t)r * DH + c * 8);
                cp_async16(Va + (uint32_t)(r * HST + c * 4) * 4u,
                           Vg + (size_t)r * SS + c * 8);
            }
        }
        CP_COMMIT();
    };

    prefetch(0, 0);
    prefetch(1, 1);

    const int rloc = wid * 16 + gid;

    // Q A-fragments to registers (canonical layout, pre-scaled)
    uint32_t qf[4][4];
    {
        const __half* Qr1 = Qb + (size_t)(q0 + rloc) * DH;
        const __half* Qr2 = Qr1 + 8 * DH;
        #pragma unroll
        for (int kb = 0; kb < 4; kb++) {
            qf[kb][0] = *(const uint32_t*)(Qr1 + kb * 16 + 2 * tig);
            qf[kb][1] = *(const uint32_t*)(Qr2 + kb * 16 + 2 * tig);
            qf[kb][2] = *(const uint32_t*)(Qr1 + kb * 16 + 8 + 2 * tig);
            qf[kb][3] = *(const uint32_t*)(Qr2 + kb * 16 + 8 + 2 * tig);
        }
    }

    float l1 = 0.f, l2 = 0.f;
    float acc[8][4] = {};

    for (int jt = 0; jt < NTILE; jt++) {
        const int st = jt % 3;
        CP_WAIT1();
        __syncthreads();
        prefetch(jt + 2, (jt + 2) % 3);
        const uint32_t Kbase = stb + (uint32_t)(st * STAGEW) * 4u;
        const uint32_t Vbase = Kbase + KW * 4u;

        // S' = Q' @ K^T   (Q' pre-scaled so P = exp2(S'))
        float sc[8][4] = {};
        #pragma unroll
        for (int kb = 0; kb < 4; kb++) {
            #pragma unroll
            for (int np = 0; np < 4; np++) {
                uint32_t bv0, bv1, bv2, bv3;
                ldsm4(bv0, bv1, bv2, bv3,
                      Kbase + (boffw + (uint32_t)(np * 16 * HST + kb * 8)) * 4u);
                mma16(sc[2*np],   qf[kb], bv0, bv1);
                mma16(sc[2*np+1], qf[kb], bv2, bv3);
            }
        }

        // PV with register-resident P
        #pragma unroll
        for (int kb = 0; kb < 4; kb++) {
            const float e00 = exp2f(sc[2*kb][0]),   e01 = exp2f(sc[2*kb][1]);
            const float e02 = exp2f(sc[2*kb][2]),   e03 = exp2f(sc[2*kb][3]);
            const float e10 = exp2f(sc[2*kb+1][0]), e11 = exp2f(sc[2*kb+1][1]);
            const float e12 = exp2f(sc[2*kb+1][2]), e13 = exp2f(sc[2*kb+1][3]);
            l1 += e00 + e01 + e10 + e11;
            l2 += e02 + e03 + e12 + e13;
            uint32_t af[4];
            af[0] = pack_h2(e00, e01);
            af[1] = pack_h2(e02, e03);
            af[2] = pack_h2(e10, e11);
            af[3] = pack_h2(e12, e13);
            #pragma unroll
            for (int np = 0; np < 4; np++) {
                uint32_t bv0, bv1, bv2, bv3;
                ldsm4(bv0, bv1, bv2, bv3,
                      Vbase + (boffw + (uint32_t)(np * 16 * HST + kb * 8)) * 4u);
                mma16(acc[2*np],   af, bv0, bv1);
                mma16(acc[2*np+1], af, bv2, bv3);
            }
        }
    }

    // final row-sum reduce + normalize + fp16 canonical store [B,S,D]
    l1 += __shfl_xor_sync(0xffffffffu, l1, 1);
    l1 += __shfl_xor_sync(0xffffffffu, l1, 2);
    l2 += __shfl_xor_sync(0xffffffffu, l2, 1);
    l2 += __shfl_xor_sync(0xffffffffu, l2, 2);
    const float inv1 = 1.0f / l1, inv2 = 1.0f / l2;
    const int r1 = q0 + rloc, r2 = r1 + 8;
    __half2* O2 = (__half2*)O;
    #pragma unroll
    for (int nt = 0; nt < 8; nt++) {
        const int w = h * 32 + nt * 4 + tig;
        O2[((size_t)b * SS + r1) * (DD / 2) + w] =
            __floats2half2_rn(acc[nt][0] * inv1, acc[nt][1] * inv1);
        O2[((size_t)b * SS + r2) * (DD / 2) + w] =
            __floats2half2_rn(acc[nt][2] * inv2, acc[nt][3] * inv2);
    }
}

// ---------------------------------------------------------------------------
extern "C" void kernel_launch(void* const* d_in, const int* in_sizes, int n_in,
                              void* d_out, int out_size) {
    const float* X  = (const float*)d_in[0];
    const float* Wq = (const float*)d_in[1];
    const float* bq = (const float*)d_in[2];
    const float* Wk = (const float*)d_in[3];
    const float* bk = (const float*)d_in[4];
    const float* Wv = (const float*)d_in[5];
    const float* bv = (const float*)d_in[6];
    const float* Wo = (const float*)d_in[7];
    const float* bo = (const float*)d_in[8];
    float* out = (float*)d_out;

    __half *dqkvh, *datth, *dwth, *dxh;
    cudaGetSymbolAddress((void**)&dqkvh, g_QKVh);
    cudaGetSymbolAddress((void**)&datth, g_atth);
    cudaGetSymbolAddress((void**)&dwth,  g_WTh);
    cudaGetSymbolAddress((void**)&dxh,   g_Xh);
    __half* dq = dqkvh;
    __half* dk = dqkvh + MATF;
    __half* dv = dqkvh + 2 * MATF;
    __half* WoT = dwth + 3 * (size_t)DD * DD;

    cudaFuncSetAttribute(attn_tc,
                         cudaFuncAttributeMaxDynamicSharedMemorySize, ATT_SMEM_BYTES);
    cudaFuncSetAttribute(gemm_tc<0>,
                         cudaFuncAttributeMaxDynamicSharedMemorySize, GEMM_SMEM_BYTES);
    cudaFuncSetAttribute(gemm_tc<1>,
                         cudaFuncAttributeMaxDynamicSharedMemorySize, GEMM_SMEM_BYTES);

    conv_half<<<(int)(MATF / (256 * 16)), 256>>>(X, dxh);
    dim3 tgrid(DD / 32, DD / 32, 4);
    transpose4<<<tgrid, 256>>>(Wq, Wk, Wv, Wo, dwth);

    dim3 qkvgrid(DD / 128, MTOT / 128, 3);   // (8, 32, 3)
    gemm_tc<0><<<qkvgrid, 256, GEMM_SMEM_BYTES>>>(dxh, dwth, bq, bk, bv, (void*)dqkvh);

    dim3 agrid(SS / 128, HH, BB);            // (16, 16, 2)
    attn_tc<<<agrid, 256, ATT_SMEM_BYTES>>>(dq, dk, dv, datth);

    dim3 ogrid(DD / 128, MTOT / 128);        // (8, 32)
    gemm_tc<1><<<ogrid, 256, GEMM_SMEM_BYTES>>>(datth, WoT, bo, nullptr, nullptr, (void*)out);
}